// round 11
// baseline (speedup 1.0000x reference)
#include <cuda_runtime.h>
#include <cuda_bf16.h>

// Problem constants
#define TT   4096
#define HH   16
#define DKK  128
#define QKVC 6144
#define NELEM (TT * HH * DKK)   // 8388608

// Scratch (static __device__ globals — no runtime allocation)
// g_P packed per (t,h): [slot0(128) | a(128) | k(128) | q(128)]
// slot0 holds ka after prep; pass2 overwrites it in place with
// w_t = ka_t ∘ a_{t-1} ∘ a_{t-2} (only warp (t,h) ever touches slot0 of (t,h)).
__device__ __align__(16) float g_P [TT * HH * 512];
__device__ __align__(16) float g_BV[NELEM];        // b * (conv+silu v)
__device__ __align__(16) float g_S4[TT * HH * 4];  // {b, R, Q, 0} per (t,h)
__device__ float g_B[TT * HH];                     // sigmoid(beta)

typedef unsigned long long ull;

// --------------------------------------------------------------------------
// f32x2 packed-math helpers (FFMA2 path; ptxas only emits via PTX f32x2)
// --------------------------------------------------------------------------
__device__ __forceinline__ ull ffma2(ull a, ull b, ull c) {
    ull d;
    asm("fma.rn.f32x2 %0, %1, %2, %3;" : "=l"(d) : "l"(a), "l"(b), "l"(c));
    return d;
}
__device__ __forceinline__ ull fmul2(ull a, ull b) {
    ull d;
    asm("mul.rn.f32x2 %0, %1, %2;" : "=l"(d) : "l"(a), "l"(b));
    return d;
}
__device__ __forceinline__ ull fadd2(ull a, ull b) {
    ull d;
    asm("add.rn.f32x2 %0, %1, %2;" : "=l"(d) : "l"(a), "l"(b));
    return d;
}
__device__ __forceinline__ float hsum2(ull a) {
    float lo, hi;
    asm("mov.b64 {%0, %1}, %2;" : "=f"(lo), "=f"(hi) : "l"(a));
    return lo + hi;
}
__device__ __forceinline__ ull pack2(float x) {
    ull d;
    asm("mov.b64 %0, {%1, %1};" : "=l"(d) : "f"(x));
    return d;
}
__device__ __forceinline__ ull packAB(float a, float b) {
    ull d;
    asm("mov.b64 %0, {%1, %2};" : "=l"(d) : "f"(a), "f"(b));
    return d;
}
__device__ __forceinline__ void unpack2(float& lo, float& hi, ull a) {
    asm("mov.b64 {%0, %1}, %2;" : "=f"(lo), "=f"(hi) : "l"(a));
}
__device__ __forceinline__ ull shfl64(ull v, int m) {
    float lo, hi;
    unpack2(lo, hi, v);
    lo = __shfl_xor_sync(0xffffffffu, lo, m);
    hi = __shfl_xor_sync(0xffffffffu, hi, m);
    return packAB(lo, hi);
}

// cp.async helper
__device__ __forceinline__ void cp16(float* dst, const float* src) {
    unsigned d = (unsigned)__cvta_generic_to_shared(dst);
    asm volatile("cp.async.cg.shared.global [%0], [%1], 16;"
                 :: "r"(d), "l"(src) : "memory");
}

// --------------------------------------------------------------------------
// Kernel 1: conv1d(K=4, depthwise, causal) + SiLU + l2norm + gate precompute
// One warp per (t, h); lane handles 4 consecutive d via float4.
// --------------------------------------------------------------------------
__device__ __forceinline__ void conv_silu4(const float* __restrict__ x,
                                           const float* __restrict__ w,
                                           int t, int c, float out[4]) {
    float wz[4][4];
#pragma unroll
    for (int j = 0; j < 4; j++) {
        float4 wv = *(const float4*)(w + (size_t)(c + j) * 4);
        wz[j][0] = wv.x; wz[j][1] = wv.y; wz[j][2] = wv.z; wz[j][3] = wv.w;
    }
    float acc[4] = {0.f, 0.f, 0.f, 0.f};
#pragma unroll
    for (int tau = 0; tau < 4; tau++) {
        int tt = t - 3 + tau;
        if (tt >= 0) {
            float4 xv = *(const float4*)(x + (size_t)tt * QKVC + c);
            acc[0] = fmaf(xv.x, wz[0][tau], acc[0]);
            acc[1] = fmaf(xv.y, wz[1][tau], acc[1]);
            acc[2] = fmaf(xv.z, wz[2][tau], acc[2]);
            acc[3] = fmaf(xv.w, wz[3][tau], acc[3]);
        }
    }
#pragma unroll
    for (int j = 0; j < 4; j++)
        out[j] = acc[j] / (1.f + expf(-acc[j]));   // SiLU
}

__global__ void prep_kernel(const float* __restrict__ qkv,
                            const float* __restrict__ fg,
                            const float* __restrict__ beta,
                            const float* __restrict__ w,
                            const float* __restrict__ A_log,
                            const float* __restrict__ dt_bias) {
    int gw   = (blockIdx.x * blockDim.x + threadIdx.x) >> 5;
    int lane = threadIdx.x & 31;
    if (gw >= TT * HH) return;
    int t = gw >> 4;
    int h = gw & 15;
    int d = lane * 4;
    int cq = h * DKK + d;

    float qy[4], ky[4], vy[4];
    conv_silu4(qkv, w, t, cq,        qy);
    conv_silu4(qkv, w, t, cq + 2048, ky);
    conv_silu4(qkv, w, t, cq + 4096, vy);

    // l2norm sums
    float sq = 0.f, sk = 0.f;
#pragma unroll
    for (int j = 0; j < 4; j++) {
        sq = fmaf(qy[j], qy[j], sq);
        sk = fmaf(ky[j], ky[j], sk);
    }
#pragma unroll
    for (int m = 16; m > 0; m >>= 1) {
        sq += __shfl_xor_sync(0xffffffffu, sq, m);
        sk += __shfl_xor_sync(0xffffffffu, sk, m);
    }
    float se_q = sq + 1e-6f, se_k = sk + 1e-6f;
    float rq = rsqrtf(se_q); rq = rq * (1.5f - 0.5f * se_q * rq * rq);  // Newton
    float rk = rsqrtf(se_k); rk = rk * (1.5f - 0.5f * se_k * rk * rk);
    rq *= 0.08838834764831845f;   // DK^-0.5

    // gate
    float ea = expf(A_log[h]);
    float4 fgv = *(const float4*)(fg + (size_t)t * (HH * DKK) + h * DKK + d);
    float4 dbv = *(const float4*)(dt_bias + h * DKK + d);
    float zf[4] = {fgv.x + dbv.x, fgv.y + dbv.y, fgv.z + dbv.z, fgv.w + dbv.w};

    float bb = 1.f / (1.f + expf(-beta[t * HH + h]));

    float qn[4], kn[4], av[4], kav[4];
#pragma unroll
    for (int j = 0; j < 4; j++) {
        float z  = zf[j];
        float sp = (z > 20.f) ? z : log1pf(expf(z));   // softplus
        av[j]  = expf(-ea * sp);                       // a = exp(g)
        qn[j]  = qy[j] * rq;
        kn[j]  = ky[j] * rk;
        kav[j] = kn[j] * av[j];
    }

    size_t pb = ((size_t)t * HH + h) * 512 + d;
    *(float4*)(g_P + pb      ) = make_float4(kav[0], kav[1], kav[2], kav[3]);
    *(float4*)(g_P + pb + 128) = make_float4(av[0],  av[1],  av[2],  av[3]);
    *(float4*)(g_P + pb + 256) = make_float4(kn[0],  kn[1],  kn[2],  kn[3]);
    *(float4*)(g_P + pb + 384) = make_float4(qn[0],  qn[1],  qn[2],  qn[3]);
    *(float4*)(g_BV + ((size_t)t * HH + h) * DKK + d) =
        make_float4(vy[0] * bb, vy[1] * bb, vy[2] * bb, vy[3] * bb);
    if (lane == 0)
        g_B[t * HH + h] = bb;
}

// --------------------------------------------------------------------------
// Kernel 1b: lookahead precompute. One warp per (t,h).
//   w_t = ka_t ∘ a_{t-1} ∘ a_{t-2}      (overwrite slot0 in place)
//   R_t = (ka_t ∘ a_{t-1}) · k_{t-2}    (scalar)
//   Q_t = ka_t · k_{t-1}                (scalar)
// Negative t indices: a := 1, k := 0.
// --------------------------------------------------------------------------
__global__ void pass2_kernel() {
    int gw   = (blockIdx.x * blockDim.x + threadIdx.x) >> 5;
    int lane = threadIdx.x & 31;
    if (gw >= TT * HH) return;
    int t = gw >> 4;
    int h = gw & 15;
    int d = lane * 4;

    size_t bt = ((size_t)t * HH + h) * 512;
    const size_t ts = (size_t)HH * 512;

    float4 ka = *(const float4*)(g_P + bt + d);
    float4 a1 = make_float4(1.f, 1.f, 1.f, 1.f);
    float4 a2 = make_float4(1.f, 1.f, 1.f, 1.f);
    float4 k1 = make_float4(0.f, 0.f, 0.f, 0.f);
    float4 k2 = make_float4(0.f, 0.f, 0.f, 0.f);
    if (t >= 1) {
        a1 = *(const float4*)(g_P + bt - ts + 128 + d);
        k1 = *(const float4*)(g_P + bt - ts + 256 + d);
    }
    if (t >= 2) {
        a2 = *(const float4*)(g_P + bt - 2 * ts + 128 + d);
        k2 = *(const float4*)(g_P + bt - 2 * ts + 256 + d);
    }
    float4 u = make_float4(ka.x * a1.x, ka.y * a1.y, ka.z * a1.z, ka.w * a1.w);
    float4 wv = make_float4(u.x * a2.x, u.y * a2.y, u.z * a2.z, u.w * a2.w);

    float rp = fmaf(u.x, k2.x, u.y * k2.y) + fmaf(u.z, k2.z, u.w * k2.w);
    float qp = fmaf(ka.x, k1.x, ka.y * k1.y) + fmaf(ka.z, k1.z, ka.w * k1.w);
#pragma unroll
    for (int m = 16; m > 0; m >>= 1) {
        rp += __shfl_xor_sync(0xffffffffu, rp, m);
        qp += __shfl_xor_sync(0xffffffffu, qp, m);
    }
    *(float4*)(g_P + bt + d) = wv;            // slot0 := w (safe: private)
    if (lane == 0)
        *(float4*)(g_S4 + ((size_t)t * HH + h) * 4) =
            make_float4(g_B[t * HH + h], rp, qp, 0.f);
}

// --------------------------------------------------------------------------
// Kernel 2: gated delta-rule recurrence with 3-step lookahead (R8 math).
// CTA = 128 threads (4 warps) = 8 v-columns; one warp = 2 v-columns.
// Grid = 256 CTAs -> ~2 CTAs/SM: independent barrier domains overlap.
// Lane owns k-quad 4*lane..4*lane+3 (distinct-per-lane LDS.128).
// 8-step groups, 32-stage ring (dynamic smem), 1 barrier per 8 steps,
// 8-16 steps of cp.async prefetch (covers DRAM latency).
//
// Critical chain per step: 3 dependent packed FFMA2s:
//   r_t = P_t + d2*R_t + d1*Q_t;  dt = bv_t - b_t*r_t
// P_{t+3} = w_{t+3}.S_t reduced off-chain (3-step slack).
// --------------------------------------------------------------------------
#define STGF 524   // floats per stage: 512 packed + 8 bv + 4 scalars
#define NSTG 32    // 4 groups x 8 steps in-flight ring
#define SMEM_BYTES (NSTG * STGF * 4)   // 67072 B (dynamic)

__global__ void __launch_bounds__(128)
recur_kernel(float* __restrict__ out) {
    extern __shared__ __align__(16) float sm[];

    const int tid  = threadIdx.x;
    const int warp = tid >> 5;
    const int lane = tid & 31;
    const int h    = blockIdx.x >> 4;             // 16 CTAs per head
    const int vb   = (blockIdx.x & 15) * 8;       // CTA's 8-column slab
    float* outp = out + h * DKK + vb + warp * 2;  // float2 per (t, warp)

    auto issue = [&](int g) {
#pragma unroll
        for (int s = 0; s < 8; s++) {
            int tu = 8 * g + s;
            float* sp = sm + (tu & 31) * STGF;
            int t = (tu > TT - 1) ? (TT - 1) : tu;
            const float* gp = g_P + ((size_t)t * HH + h) * 512;
            cp16(sp + tid * 4, gp + tid * 4);     // 128 thr x 16B = 2KB
            if (tid < 2)
                cp16(sp + 512 + tid * 4,
                     g_BV + ((size_t)t * HH + h) * DKK + vb + tid * 4);
            else if (tid == 2)
                cp16(sp + 520, g_S4 + ((size_t)t * HH + h) * 4);
        }
        asm volatile("cp.async.commit_group;" ::: "memory");
    };

    issue(0); issue(1); issue(2);

    ull SA0 = 0, SA1 = 0, SB0 = 0, SB1 = 0;
    ull Pq[4] = {0, 0, 0, 0};     // packed reduced P for steps t..t+3
    ull d1 = 0, d2 = 0;           // packed delta_{t-1}, delta_{t-2}

    for (int g = 0; g < TT / 8; g++) {
        // groups <= g+1 complete (w of t+3 may live in group g+1)
        asm volatile("cp.async.wait_group 1;" ::: "memory");
        __syncthreads();
#pragma unroll
        for (int s = 0; s < 8; s++) {
            const int t = 8 * g + s;
            const float* spb = sm + (t & 31) * STGF;
            const float* spn = sm + ((t + 3) & 31) * STGF;  // w_{t+3}
            const int lo = lane * 4;

            // distinct-per-lane array loads (one LDS.128 per array)
            ulonglong2 A = *(const ulonglong2*)(spb + 128 + lo);
            ulonglong2 K = *(const ulonglong2*)(spb + 256 + lo);
            ulonglong2 Q = *(const ulonglong2*)(spb + 384 + lo);
            ulonglong2 W = *(const ulonglong2*)(spn + lo);

            float4 s4 = *(const float4*)(spb + 520);    // {b, R, Q, -}
            ull R2  = pack2(s4.y);
            ull Q2  = pack2(s4.z);
            ull nB2 = pack2(-s4.x);
            ull BV2 = *(const ull*)(spb + 512 + warp * 2);  // (colA,colB)

            // ---- critical chain: 3 dependent packed FFMA2s ----
            ull r  = ffma2(d2, R2, Pq[t & 3]);
            r      = ffma2(d1, Q2, r);
            ull dt = ffma2(nB2, r, BV2);
            d2 = d1; d1 = dt;
            float dA, dB; unpack2(dA, dB, dt);
            ull DA = pack2(dA), DB = pack2(dB);

            // ---- off-chain: S update + o-dot + P_{t+3}-dot ----
            SA0 = ffma2(A.x, SA0, fmul2(K.x, DA));
            SA1 = ffma2(A.y, SA1, fmul2(K.y, DA));
            SB0 = ffma2(A.x, SB0, fmul2(K.x, DB));
            SB1 = ffma2(A.y, SB1, fmul2(K.y, DB));

            float oA = hsum2(ffma2(Q.x, SA0, fmul2(Q.y, SA1)));
            float oB = hsum2(ffma2(Q.x, SB0, fmul2(Q.y, SB1)));
            float pA = hsum2(ffma2(W.x, SA0, fmul2(W.y, SA1)));
            float pB = hsum2(ffma2(W.x, SB0, fmul2(W.y, SB1)));
            ull ov = packAB(oA, oB);
            ull pv = packAB(pA, pB);

            // 5-level butterfly over all 32 lanes; two interleaved chains
#pragma unroll
            for (int m = 1; m < 32; m <<= 1) {
                ov = fadd2(ov, shfl64(ov, m));
                pv = fadd2(pv, shfl64(pv, m));
            }
            Pq[(t + 3) & 3] = pv;          // P_{t+3} = w_{t+3} . S_t
            if (lane == 0) {
                float xA, xB; unpack2(xA, xB, ov);
                *(float2*)(outp + (size_t)t * (HH * DKK)) = make_float2(xA, xB);
            }
        }
        issue(g + 3);
    }
}

// --------------------------------------------------------------------------
extern "C" void kernel_launch(void* const* d_in, const int* in_sizes, int n_in,
                              void* d_out, int out_size) {
    const float* mixed_qkv   = (const float*)d_in[0];
    const float* forget_gate = (const float*)d_in[1];
    const float* beta        = (const float*)d_in[2];
    const float* conv_w      = (const float*)d_in[3];
    const float* A_log       = (const float*)d_in[4];
    const float* dt_bias     = (const float*)d_in[5];
    float* out = (float*)d_out;

    cudaFuncSetAttribute(recur_kernel,
                         cudaFuncAttributeMaxDynamicSharedMemorySize,
                         SMEM_BYTES);

    prep_kernel<<<(TT * HH) / 8, 256>>>(mixed_qkv, forget_gate, beta,
                                        conv_w, A_log, dt_bias);
    pass2_kernel<<<(TT * HH) / 8, 256>>>();
    recur_kernel<<<256, 128, SMEM_BYTES>>>(out);
}

// round 12
// speedup vs baseline: 1.1935x; 1.1935x over previous
#include <cuda_runtime.h>
#include <cuda_bf16.h>

// Problem constants
#define TT   4096
#define HH   16
#define DKK  128
#define QKVC 6144
#define NELEM (TT * HH * DKK)   // 8388608

// Scratch (static __device__ globals — no runtime allocation)
// g_P packed per (t,h): [slot0(128) | a(128) | k(128) | q(128)]
// slot0 holds ka after prep; pass2 overwrites it in place with
// w_t = ka_t ∘ a_{t-1} ∘ a_{t-2} (only warp (t,h) ever touches slot0 of (t,h)).
__device__ __align__(16) float g_P [TT * HH * 512];
__device__ __align__(16) float g_BV[NELEM];        // b * (conv+silu v)
__device__ __align__(16) float g_S4[TT * HH * 4];  // {b, R, Q, 0} per (t,h)
__device__ float g_B[TT * HH];                     // sigmoid(beta)

typedef unsigned long long ull;

// --------------------------------------------------------------------------
// f32x2 packed-math helpers (FFMA2 path; ptxas only emits via PTX f32x2)
// --------------------------------------------------------------------------
__device__ __forceinline__ ull ffma2(ull a, ull b, ull c) {
    ull d;
    asm("fma.rn.f32x2 %0, %1, %2, %3;" : "=l"(d) : "l"(a), "l"(b), "l"(c));
    return d;
}
__device__ __forceinline__ ull fmul2(ull a, ull b) {
    ull d;
    asm("mul.rn.f32x2 %0, %1, %2;" : "=l"(d) : "l"(a), "l"(b));
    return d;
}
__device__ __forceinline__ ull fadd2(ull a, ull b) {
    ull d;
    asm("add.rn.f32x2 %0, %1, %2;" : "=l"(d) : "l"(a), "l"(b));
    return d;
}
__device__ __forceinline__ float hsum2(ull a) {
    float lo, hi;
    asm("mov.b64 {%0, %1}, %2;" : "=f"(lo), "=f"(hi) : "l"(a));
    return lo + hi;
}
__device__ __forceinline__ ull pack2(float x) {
    ull d;
    asm("mov.b64 %0, {%1, %1};" : "=l"(d) : "f"(x));
    return d;
}
__device__ __forceinline__ ull packAB(float a, float b) {
    ull d;
    asm("mov.b64 %0, {%1, %2};" : "=l"(d) : "f"(a), "f"(b));
    return d;
}
__device__ __forceinline__ void unpack2(float& lo, float& hi, ull a) {
    asm("mov.b64 {%0, %1}, %2;" : "=f"(lo), "=f"(hi) : "l"(a));
}
__device__ __forceinline__ ull shfl64(ull v, int m) {
    float lo, hi;
    unpack2(lo, hi, v);
    lo = __shfl_xor_sync(0xffffffffu, lo, m);
    hi = __shfl_xor_sync(0xffffffffu, hi, m);
    return packAB(lo, hi);
}

// cp.async helper
__device__ __forceinline__ void cp16(float* dst, const float* src) {
    unsigned d = (unsigned)__cvta_generic_to_shared(dst);
    asm volatile("cp.async.cg.shared.global [%0], [%1], 16;"
                 :: "r"(d), "l"(src) : "memory");
}

// --------------------------------------------------------------------------
// Kernel 1: conv1d(K=4, depthwise, causal) + SiLU + l2norm + gate precompute.
// One warp per (t-group of 4, h); lane owns 4 consecutive d channels.
// Sliding register window: 4-deep float4 ring per segment reuses rows across
// the 4 timesteps (21 row loads + 12 weight loads per 4 outputs, vs 48+48).
// t0 % 4 == 0, so ring indices (t-3+tau)&3 are compile-time constants.
// --------------------------------------------------------------------------
__global__ void __launch_bounds__(256)
prep_kernel(const float* __restrict__ qkv,
            const float* __restrict__ fg,
            const float* __restrict__ beta,
            const float* __restrict__ w,
            const float* __restrict__ A_log,
            const float* __restrict__ dt_bias) {
    int gw   = (blockIdx.x * blockDim.x + threadIdx.x) >> 5;
    int lane = threadIdx.x & 31;
    if (gw >= TT * HH / 4) return;
    int t0 = (gw >> 4) << 2;     // multiple of 4
    int h  = gw & 15;
    int d  = lane * 4;
    int cq = h * DKK + d;
    int ck = cq + 2048;
    int cv = cq + 4096;

    // depthwise weights: [channel][tau], 4 channels x 3 segments
    float wzq[4][4], wzk[4][4], wzv[4][4];
#pragma unroll
    for (int j = 0; j < 4; j++) {
        float4 a = *(const float4*)(w + (size_t)(cq + j) * 4);
        float4 b = *(const float4*)(w + (size_t)(ck + j) * 4);
        float4 c = *(const float4*)(w + (size_t)(cv + j) * 4);
        wzq[j][0] = a.x; wzq[j][1] = a.y; wzq[j][2] = a.z; wzq[j][3] = a.w;
        wzk[j][0] = b.x; wzk[j][1] = b.y; wzk[j][2] = b.z; wzk[j][3] = b.w;
        wzv[j][0] = c.x; wzv[j][1] = c.y; wzv[j][2] = c.z; wzv[j][3] = c.w;
    }

    float  ea  = expf(A_log[h]);
    float4 dbv = *(const float4*)(dt_bias + h * DKK + d);

    // rolling window (ring slot = row & 3)
    float4 xq[4], xk[4], xv[4];
    const float4 z4 = make_float4(0.f, 0.f, 0.f, 0.f);
#pragma unroll
    for (int i = 1; i <= 3; i++) {   // rows t0-3 .. t0-1 (ring slots 1,2,3)
        int r = t0 - 4 + i;
        if (r >= 0) {
            xq[i] = *(const float4*)(qkv + (size_t)r * QKVC + cq);
            xk[i] = *(const float4*)(qkv + (size_t)r * QKVC + ck);
            xv[i] = *(const float4*)(qkv + (size_t)r * QKVC + cv);
        } else { xq[i] = z4; xk[i] = z4; xv[i] = z4; }
    }

#pragma unroll
    for (int i = 0; i < 4; i++) {
        const int t  = t0 + i;
        const int ri = i & 3;        // ring slot of row t
        xq[ri] = *(const float4*)(qkv + (size_t)t * QKVC + cq);
        xk[ri] = *(const float4*)(qkv + (size_t)t * QKVC + ck);
        xv[ri] = *(const float4*)(qkv + (size_t)t * QKVC + cv);

        float qy[4] = {0,0,0,0}, ky[4] = {0,0,0,0}, vy[4] = {0,0,0,0};
#pragma unroll
        for (int tau = 0; tau < 4; tau++) {
            const int rs = (i + tau + 1) & 3;   // (t-3+tau) & 3
            const float4 aq = xq[rs], ak = xk[rs], av4 = xv[rs];
            qy[0] = fmaf(aq.x, wzq[0][tau], qy[0]);
            qy[1] = fmaf(aq.y, wzq[1][tau], qy[1]);
            qy[2] = fmaf(aq.z, wzq[2][tau], qy[2]);
            qy[3] = fmaf(aq.w, wzq[3][tau], qy[3]);
            ky[0] = fmaf(ak.x, wzk[0][tau], ky[0]);
            ky[1] = fmaf(ak.y, wzk[1][tau], ky[1]);
            ky[2] = fmaf(ak.z, wzk[2][tau], ky[2]);
            ky[3] = fmaf(ak.w, wzk[3][tau], ky[3]);
            vy[0] = fmaf(av4.x, wzv[0][tau], vy[0]);
            vy[1] = fmaf(av4.y, wzv[1][tau], vy[1]);
            vy[2] = fmaf(av4.z, wzv[2][tau], vy[2]);
            vy[3] = fmaf(av4.w, wzv[3][tau], vy[3]);
        }
#pragma unroll
        for (int j = 0; j < 4; j++) {
            qy[j] = qy[j] / (1.f + expf(-qy[j]));   // SiLU
            ky[j] = ky[j] / (1.f + expf(-ky[j]));
            vy[j] = vy[j] / (1.f + expf(-vy[j]));
        }

        // l2norm sums
        float sq = 0.f, sk = 0.f;
#pragma unroll
        for (int j = 0; j < 4; j++) {
            sq = fmaf(qy[j], qy[j], sq);
            sk = fmaf(ky[j], ky[j], sk);
        }
#pragma unroll
        for (int m = 16; m > 0; m >>= 1) {
            sq += __shfl_xor_sync(0xffffffffu, sq, m);
            sk += __shfl_xor_sync(0xffffffffu, sk, m);
        }
        float se_q = sq + 1e-6f, se_k = sk + 1e-6f;
        float rq = rsqrtf(se_q); rq = rq * (1.5f - 0.5f * se_q * rq * rq);
        float rk = rsqrtf(se_k); rk = rk * (1.5f - 0.5f * se_k * rk * rk);
        rq *= 0.08838834764831845f;   // DK^-0.5

        // gate
        float4 fgv = *(const float4*)(fg + (size_t)t * (HH * DKK) + h * DKK + d);
        float zf[4] = {fgv.x + dbv.x, fgv.y + dbv.y, fgv.z + dbv.z, fgv.w + dbv.w};
        float bb = 1.f / (1.f + expf(-beta[t * HH + h]));

        float qn[4], kn[4], av[4], kav[4];
#pragma unroll
        for (int j = 0; j < 4; j++) {
            float z  = zf[j];
            float sp = (z > 20.f) ? z : log1pf(expf(z));   // softplus
            av[j]  = expf(-ea * sp);                       // a = exp(g)
            qn[j]  = qy[j] * rq;
            kn[j]  = ky[j] * rk;
            kav[j] = kn[j] * av[j];
        }

        size_t pb = ((size_t)t * HH + h) * 512 + d;
        *(float4*)(g_P + pb      ) = make_float4(kav[0], kav[1], kav[2], kav[3]);
        *(float4*)(g_P + pb + 128) = make_float4(av[0],  av[1],  av[2],  av[3]);
        *(float4*)(g_P + pb + 256) = make_float4(kn[0],  kn[1],  kn[2],  kn[3]);
        *(float4*)(g_P + pb + 384) = make_float4(qn[0],  qn[1],  qn[2],  qn[3]);
        *(float4*)(g_BV + ((size_t)t * HH + h) * DKK + d) =
            make_float4(vy[0] * bb, vy[1] * bb, vy[2] * bb, vy[3] * bb);
        if (lane == 0)
            g_B[t * HH + h] = bb;
    }
}

// --------------------------------------------------------------------------
// Kernel 1b: lookahead precompute. One warp per (t,h).
//   w_t = ka_t ∘ a_{t-1} ∘ a_{t-2}      (overwrite slot0 in place)
//   R_t = (ka_t ∘ a_{t-1}) · k_{t-2}    (scalar)
//   Q_t = ka_t · k_{t-1}                (scalar)
// Negative t indices: a := 1, k := 0.
// --------------------------------------------------------------------------
__global__ void pass2_kernel() {
    int gw   = (blockIdx.x * blockDim.x + threadIdx.x) >> 5;
    int lane = threadIdx.x & 31;
    if (gw >= TT * HH) return;
    int t = gw >> 4;
    int h = gw & 15;
    int d = lane * 4;

    size_t bt = ((size_t)t * HH + h) * 512;
    const size_t ts = (size_t)HH * 512;

    float4 ka = *(const float4*)(g_P + bt + d);
    float4 a1 = make_float4(1.f, 1.f, 1.f, 1.f);
    float4 a2 = make_float4(1.f, 1.f, 1.f, 1.f);
    float4 k1 = make_float4(0.f, 0.f, 0.f, 0.f);
    float4 k2 = make_float4(0.f, 0.f, 0.f, 0.f);
    if (t >= 1) {
        a1 = *(const float4*)(g_P + bt - ts + 128 + d);
        k1 = *(const float4*)(g_P + bt - ts + 256 + d);
    }
    if (t >= 2) {
        a2 = *(const float4*)(g_P + bt - 2 * ts + 128 + d);
        k2 = *(const float4*)(g_P + bt - 2 * ts + 256 + d);
    }
    float4 u = make_float4(ka.x * a1.x, ka.y * a1.y, ka.z * a1.z, ka.w * a1.w);
    float4 wv = make_float4(u.x * a2.x, u.y * a2.y, u.z * a2.z, u.w * a2.w);

    float rp = fmaf(u.x, k2.x, u.y * k2.y) + fmaf(u.z, k2.z, u.w * k2.w);
    float qp = fmaf(ka.x, k1.x, ka.y * k1.y) + fmaf(ka.z, k1.z, ka.w * k1.w);
#pragma unroll
    for (int m = 16; m > 0; m >>= 1) {
        rp += __shfl_xor_sync(0xffffffffu, rp, m);
        qp += __shfl_xor_sync(0xffffffffu, qp, m);
    }
    *(float4*)(g_P + bt + d) = wv;            // slot0 := w (safe: private)
    if (lane == 0)
        *(float4*)(g_S4 + ((size_t)t * HH + h) * 4) =
            make_float4(g_B[t * HH + h], rp, qp, 0.f);
}

// --------------------------------------------------------------------------
// Kernel 2: gated delta-rule recurrence with 3-step lookahead (R8 math,
// R8 grid: 128 CTAs x 256 thr = 16 cols/CTA, warp = 2 cols).
// Change vs R8: 8-step groups + 32-stage ring (dynamic smem) -> one
// wait_group+__syncthreads per 8 steps instead of per 4.
// Lane owns k-quad 4*lane..4*lane+3 (distinct-per-lane LDS.128).
// Critical chain per step: 3 dependent packed FFMA2s:
//   r_t = P_t + d2*R_t + d1*Q_t;  dt = bv_t - b_t*r_t
// P_{t+3} = w_{t+3}.S_t reduced off-chain (3-step slack).
// --------------------------------------------------------------------------
#define STGF 544   // floats per stage: 512 packed + 16 bv + 4 scalars + pad
#define NSTG 32    // 4 groups x 8 steps in-flight ring
#define SMEM_BYTES (NSTG * STGF * 4)   // 69632 B (dynamic)

__global__ void __launch_bounds__(256)
recur_kernel(float* __restrict__ out) {
    extern __shared__ __align__(16) float sm[];

    const int tid  = threadIdx.x;
    const int warp = tid >> 5;
    const int lane = tid & 31;
    const int h    = blockIdx.x >> 3;
    const int vb   = (blockIdx.x & 7) * 16;       // CTA's 16-column slab
    float* outp = out + h * DKK + vb + warp * 2;  // float2 per (t, warp)

    auto issue = [&](int g) {
#pragma unroll
        for (int s = 0; s < 8; s++) {
            int tu = 8 * g + s;
            float* sp = sm + (tu & 31) * STGF;
            int t = (tu > TT - 1) ? (TT - 1) : tu;
            const float* gp = g_P + ((size_t)t * HH + h) * 512;
            if (tid < 128) cp16(sp + tid * 4, gp + tid * 4);
            if (tid >= 128 && tid < 132)
                cp16(sp + 512 + (tid - 128) * 4,
                     g_BV + ((size_t)t * HH + h) * DKK + vb + (tid - 128) * 4);
            if (tid == 132)
                cp16(sp + 528, g_S4 + ((size_t)t * HH + h) * 4);
        }
        asm volatile("cp.async.commit_group;" ::: "memory");
    };

    issue(0); issue(1); issue(2);

    ull SA0 = 0, SA1 = 0, SB0 = 0, SB1 = 0;
    ull Pq[4] = {0, 0, 0, 0};     // packed reduced P for steps t..t+3
    ull d1 = 0, d2 = 0;           // packed delta_{t-1}, delta_{t-2}

    for (int g = 0; g < TT / 8; g++) {
        // groups <= g+1 complete (w of t+3 may live in group g+1)
        asm volatile("cp.async.wait_group 1;" ::: "memory");
        __syncthreads();
#pragma unroll
        for (int s = 0; s < 8; s++) {
            const int t = 8 * g + s;
            const float* spb = sm + (t & 31) * STGF;
            const float* spn = sm + ((t + 3) & 31) * STGF;  // w_{t+3}
            const int lo = lane * 4;

            // distinct-per-lane array loads (one LDS.128 per array)
            ulonglong2 A = *(const ulonglong2*)(spb + 128 + lo);
            ulonglong2 K = *(const ulonglong2*)(spb + 256 + lo);
            ulonglong2 Q = *(const ulonglong2*)(spb + 384 + lo);
            ulonglong2 W = *(const ulonglong2*)(spn + lo);

            float4 s4 = *(const float4*)(spb + 528);    // {b, R, Q, -}
            ull R2  = pack2(s4.y);
            ull Q2  = pack2(s4.z);
            ull nB2 = pack2(-s4.x);
            ull BV2 = *(const ull*)(spb + 512 + warp * 2);  // (colA,colB)

            // ---- critical chain: 3 dependent packed FFMA2s ----
            ull r  = ffma2(d2, R2, Pq[t & 3]);
            r      = ffma2(d1, Q2, r);
            ull dt = ffma2(nB2, r, BV2);
            d2 = d1; d1 = dt;
            float dA, dB; unpack2(dA, dB, dt);
            ull DA = pack2(dA), DB = pack2(dB);

            // ---- off-chain: S update + o-dot + P_{t+3}-dot ----
            SA0 = ffma2(A.x, SA0, fmul2(K.x, DA));
            SA1 = ffma2(A.y, SA1, fmul2(K.y, DA));
            SB0 = ffma2(A.x, SB0, fmul2(K.x, DB));
            SB1 = ffma2(A.y, SB1, fmul2(K.y, DB));

            float oA = hsum2(ffma2(Q.x, SA0, fmul2(Q.y, SA1)));
            float oB = hsum2(ffma2(Q.x, SB0, fmul2(Q.y, SB1)));
            float pA = hsum2(ffma2(W.x, SA0, fmul2(W.y, SA1)));
            float pB = hsum2(ffma2(W.x, SB0, fmul2(W.y, SB1)));
            ull ov = packAB(oA, oB);
            ull pv = packAB(pA, pB);

            // 5-level butterfly over all 32 lanes; two interleaved chains
#pragma unroll
            for (int m = 1; m < 32; m <<= 1) {
                ov = fadd2(ov, shfl64(ov, m));
                pv = fadd2(pv, shfl64(pv, m));
            }
            Pq[(t + 3) & 3] = pv;          // P_{t+3} = w_{t+3} . S_t
            if (lane == 0) {
                float xA, xB; unpack2(xA, xB, ov);
                *(float2*)(outp + (size_t)t * (HH * DKK)) = make_float2(xA, xB);
            }
        }
        issue(g + 3);
    }
}

// --------------------------------------------------------------------------
extern "C" void kernel_launch(void* const* d_in, const int* in_sizes, int n_in,
                              void* d_out, int out_size) {
    const float* mixed_qkv   = (const float*)d_in[0];
    const float* forget_gate = (const float*)d_in[1];
    const float* beta        = (const float*)d_in[2];
    const float* conv_w      = (const float*)d_in[3];
    const float* A_log       = (const float*)d_in[4];
    const float* dt_bias     = (const float*)d_in[5];
    float* out = (float*)d_out;

    cudaFuncSetAttribute(recur_kernel,
                         cudaFuncAttributeMaxDynamicSharedMemorySize,
                         SMEM_BYTES);

    // 16384 (t-group, h) warps, 8 per 256-thread block
    prep_kernel<<<(TT * HH / 4) / 8, 256>>>(mixed_qkv, forget_gate, beta,
                                            conv_w, A_log, dt_bias);
    pass2_kernel<<<(TT * HH) / 8, 256>>>();
    recur_kernel<<<128, 256, SMEM_BYTES>>>(out);
}